// round 8
// baseline (speedup 1.0000x reference)
#include <cuda_runtime.h>

#define BATCH 16
#define LEN   512
#define IDIM  300
#define HDIM  32
#define ODIM  15
#define GDIM  96
#define JH    256         // keys per attention block (half)
#define TI2   32          // i-rows per attention block
#define KSTR  36          // smem row stride (floats), 16B-aligned, conflict-free

typedef unsigned long long ull;

// Scratch as float4 arrays (guarantees 16B alignment for vector access)
__device__ float4 g_gx4 [BATCH * LEN * GDIM / 4];
__device__ float4 g_out4[BATCH * LEN * HDIM / 4];
__device__ float4 g_qh4 [BATCH * LEN * HDIM / 4];
__device__ float4 g_kh4 [BATCH * LEN * HDIM / 4];
#define g_gx  ((float*)g_gx4)
#define g_out ((float*)g_out4)
#define g_qh  ((float*)g_qh4)
#define g_kh  ((float*)g_kh4)

// attention partials
__device__ float g_ps  [BATCH * 2 * LEN];            // partial ssum
__device__ float g_pc  [BATCH * 2 * LEN * HDIM];     // partial ctx
__device__ float g_osum[BATCH * 2 * HDIM];           // partial out-sums

__device__ __forceinline__ float tanh_fast(float x) {
    float y;
    asm("tanh.approx.f32 %0, %1;" : "=f"(y) : "f"(x));
    return y;
}
__device__ __forceinline__ ull ffma2u(ull a, ull b, ull c) {
    ull d;
    asm("fma.rn.f32x2 %0, %1, %2, %3;" : "=l"(d) : "l"(a), "l"(b), "l"(c));
    return d;
}
__device__ __forceinline__ ull add2u(ull a, ull b) {
    ull d;
    asm("add.rn.f32x2 %0, %1, %2;" : "=l"(d) : "l"(a), "l"(b));
    return d;
}
__device__ __forceinline__ ull pack2(float lo, float hi) {
    ull d;
    asm("mov.b64 %0, {%1, %2};" : "=l"(d) : "f"(lo), "f"(hi));
    return d;
}
__device__ __forceinline__ float hsum2(ull a) {
    float lo, hi;
    asm("mov.b64 {%0, %1}, %2;" : "=f"(lo), "=f"(hi) : "l"(a));
    return lo + hi;
}

// ---------------------------------------------------------------------------
// K1: gx = x @ w_ih^T + b_ih   (M=8192, N=96, K=300)
// ---------------------------------------------------------------------------
__global__ __launch_bounds__(256) void gx_kernel(
    const float* __restrict__ x,
    const float* __restrict__ w_ih,
    const float* __restrict__ b_ih)
{
    __shared__ float xs[16][65];
    __shared__ float ws[16][97];

    const int m0 = blockIdx.x * 64;
    const int tx = threadIdx.x & 15;
    const int ty = threadIdx.x >> 4;

    float acc[4][6];
#pragma unroll
    for (int i = 0; i < 4; i++)
#pragma unroll
        for (int j = 0; j < 6; j++) acc[i][j] = 0.f;

    for (int kt = 0; kt < IDIM; kt += 16) {
        for (int idx = threadIdx.x; idx < 64 * 16; idx += 256) {
            int r = idx >> 4, kk = idx & 15;
            int k = kt + kk;
            xs[kk][r] = (k < IDIM) ? x[(m0 + r) * IDIM + k] : 0.f;
        }
        for (int idx = threadIdx.x; idx < 96 * 16; idx += 256) {
            int c = idx >> 4, kk = idx & 15;
            int k = kt + kk;
            ws[kk][c] = (k < IDIM) ? w_ih[c * IDIM + k] : 0.f;
        }
        __syncthreads();
#pragma unroll
        for (int kk = 0; kk < 16; kk++) {
            float xv[4], wv[6];
#pragma unroll
            for (int i = 0; i < 4; i++) xv[i] = xs[kk][ty * 4 + i];
#pragma unroll
            for (int j = 0; j < 6; j++) wv[j] = ws[kk][tx * 6 + j];
#pragma unroll
            for (int i = 0; i < 4; i++)
#pragma unroll
                for (int j = 0; j < 6; j++)
                    acc[i][j] = fmaf(xv[i], wv[j], acc[i][j]);
        }
        __syncthreads();
    }
#pragma unroll
    for (int i = 0; i < 4; i++) {
        int m = m0 + ty * 4 + i;
#pragma unroll
        for (int j = 0; j < 6; j++) {
            int c = tx * 6 + j;
            g_gx[m * GDIM + c] = acc[i][j] + b_ih[c];
        }
    }
}

// ---------------------------------------------------------------------------
// K2: GRU recurrence. One warp per batch. Packed-pair shfl broadcast,
// FFMA2 split chains, depth-8 gx prefetch. No smem, no barriers.
// ---------------------------------------------------------------------------
__global__ __launch_bounds__(32) void gru_kernel(
    const float* __restrict__ w_hh,
    const float* __restrict__ b_hh,
    const float* __restrict__ h0,
    const int*   __restrict__ x_lens)
{
    const int b = blockIdx.x;
    const int h = threadIdx.x;

    const ull* w8 = (const ull*)w_hh;   // [96][16] packed pairs
    ull wr2[16], wz2[16], wn2[16];
#pragma unroll
    for (int k = 0; k < 16; k++) {
        wr2[k] = w8[(0 * HDIM + h) * 16 + k];
        wz2[k] = w8[(1 * HDIM + h) * 16 + k];
        wn2[k] = w8[(2 * HDIM + h) * 16 + k];
    }
    const ull brp = pack2(b_hh[h], 0.f);
    const ull bzp = pack2(b_hh[HDIM + h], 0.f);
    const ull bnp = pack2(b_hh[2 * HDIM + h], 0.f);

    float hcur = h0[b * HDIM + h];
    float nb0 = __shfl_xor_sync(0xffffffffu, hcur, 1);
    ull hpair = (h & 1) ? pack2(nb0, hcur) : pack2(hcur, nb0);

    const int len = x_lens[b];
    const float* gxb = g_gx + (size_t)b * LEN * GDIM;
    float* outb = g_out + (size_t)b * LEN * HDIM;

    // depth-8 prefetch of gx
    float rxb[8], zxb[8], nxb[8];
#pragma unroll
    for (int t = 0; t < 8; t++) {
        const float* p = gxb + t * GDIM;
        rxb[t] = p[h]; zxb[t] = p[HDIM + h]; nxb[t] = p[2 * HDIM + h];
    }

#pragma unroll 8
    for (int t = 0; t < LEN; t++) {
        const int s = t & 7;
        const float rx = rxb[s], zx = zxb[s], nx = nxb[s];
        if (t + 8 < LEN) {
            const float* p = gxb + (t + 8) * GDIM;
            rxb[s] = p[h]; zxb[s] = p[HDIM + h]; nxb[s] = p[2 * HDIM + h];
        }

        ull ra[4] = {brp, 0ull, 0ull, 0ull};
        ull za[4] = {bzp, 0ull, 0ull, 0ull};
        ull na[4] = {bnp, 0ull, 0ull, 0ull};
#pragma unroll
        for (int k = 0; k < 16; k++) {
            const ull h2 = __shfl_sync(0xffffffffu, hpair, 2 * k);
            const int p = k & 3;
            ra[p] = ffma2u(wr2[k], h2, ra[p]);
            za[p] = ffma2u(wz2[k], h2, za[p]);
            na[p] = ffma2u(wn2[k], h2, na[p]);
        }
        const float rh = hsum2(add2u(add2u(ra[0], ra[1]), add2u(ra[2], ra[3])));
        const float zh = hsum2(add2u(add2u(za[0], za[1]), add2u(za[2], za[3])));
        const float nh = hsum2(add2u(add2u(na[0], na[1]), add2u(na[2], na[3])));

        const float r = fmaf(tanh_fast((rx + rh) * 0.5f), 0.5f, 0.5f);
        const float z = fmaf(tanh_fast((zx + zh) * 0.5f), 0.5f, 0.5f);
        const float n = tanh_fast(fmaf(r, nh, nx));
        hcur = fmaf(z, hcur - n, n);

        const float nb = __shfl_xor_sync(0xffffffffu, hcur, 1);
        hpair = (h & 1) ? pack2(nb, hcur) : pack2(hcur, nb);

        outb[t * HDIM + h] = (t < len) ? hcur : 0.f;
    }
}

// ---------------------------------------------------------------------------
// K3: qh = out@fch_w^T, kh = out@fco_w^T
// ---------------------------------------------------------------------------
__global__ __launch_bounds__(256) void qk_kernel(
    const float* __restrict__ fch_w,
    const float* __restrict__ fco_w)
{
    __shared__ float wq[HDIM][HDIM + 1];
    __shared__ float wk[HDIM][HDIM + 1];
    __shared__ float os[8][HDIM];

    const int tid = threadIdx.x;
    for (int idx = tid; idx < HDIM * HDIM; idx += 256) {
        int c = idx >> 5, k = idx & 31;
        wq[k][c] = fch_w[c * HDIM + k];
        wk[k][c] = fco_w[c * HDIM + k];
    }
    const int m0 = blockIdx.x * 8;
    const int r = tid >> 5, c = tid & 31;
    os[r][c] = g_out[(m0 + r) * HDIM + c];
    __syncthreads();

    float aq = 0.f, ak = 0.f;
#pragma unroll
    for (int k = 0; k < HDIM; k++) {
        float o = os[r][k];
        aq = fmaf(o, wq[k][c], aq);
        ak = fmaf(o, wk[k][c], ak);
    }
    g_qh[(m0 + r) * HDIM + c] = aq;
    g_kh[(m0 + r) * HDIM + c] = ak;
}

// ---------------------------------------------------------------------------
// K4a: attention pass 1, register-lean: (q,v) pairs read from per-warp smem
// as broadcast LDS.64; target 2 blocks/SM.
// ---------------------------------------------------------------------------
__global__ __launch_bounds__(512, 2) void attn1_kernel(
    const float* __restrict__ v,
    const int*   __restrict__ x_lens)
{
    extern __shared__ float sm[];
    float*  ks   = sm;                    // [256][36]
    float*  os   = ks + JH * KSTR;        // [256][36]
    float*  vsh  = os + JH * KSTR;        // 32
    float*  red  = vsh + 32;              // [16][33]
    float2* vqsh = (float2*)(red + 16 * 33 + 8);  // [16][33] float2, per warp

    const int b    = blockIdx.z;
    const int half = blockIdx.y;
    const int i0   = blockIdx.x * TI2;
    const int tid  = threadIdx.x;
    const int wid  = tid >> 5, lane = tid & 31;
    const int jbase = b * LEN + half * JH;

    for (int idx = tid; idx < JH * 8; idx += 512) {
        int j = idx >> 3, q = idx & 7;
        float4 kv = g_kh4[(jbase + j) * 8 + q];
        float4 ov = g_out4[(jbase + j) * 8 + q];
        *(float4*)(ks + j * KSTR + q * 4) = kv;
        *(float4*)(os + j * KSTR + q * 4) = ov;
    }
    if (tid < HDIM) vsh[tid] = v[tid];
    __syncthreads();

    // partial osum (only i_tile 0 blocks)
    if (blockIdx.x == 0) {
        float p = 0.f;
#pragma unroll
        for (int jj = 0; jj < JH / 16; jj++)
            p += os[(wid * (JH / 16) + jj) * KSTR + lane];
        red[wid * 33 + lane] = p;
        __syncthreads();
        if (tid < HDIM) {
            float t = 0.f;
#pragma unroll
            for (int w = 0; w < 16; w++) t += red[w * 33 + tid];
            g_osum[(b * 2 + half) * HDIM + tid] = t;
        }
    }

    const int len    = x_lens[b];                       // len >= 256 always
    const int kcount = (half == 0) ? JH : (len - JH);   // valid keys here
    const int chunks = (kcount + 31) >> 5;
    const int tail   = JH - chunks * 32;                // fully-padded rows

    const float vl = vsh[lane];
    float S = fabsf(vl);
#pragma unroll
    for (int s = 16; s > 0; s >>= 1)
        S += __shfl_xor_sync(0xffffffffu, S, s);

    float2* vqw = vqsh + wid * 33;

    for (int ii = wid; ii < TI2; ii += 16) {
        const int i = i0 + ii;

        // stage (q_h, v_h) pairs for this warp's row
        const float ql = g_qh[(size_t)(b * LEN + i) * HDIM + lane];
        vqw[lane] = make_float2(ql, vl);
        __syncwarp();

        float ep = 0.f;
        if (tail > 0) {
            ep = vl * tanh_fast(ql);
#pragma unroll
            for (int s = 16; s > 0; s >>= 1)
                ep += __shfl_xor_sync(0xffffffffu, ep, s);
        }

        float ssum = 0.f, ctx = 0.f;
        for (int c = 0; c < chunks; c++) {
            const float4* krow4 = (const float4*)(ks + (c * 32 + lane) * KSTR);
            float e = 0.f;
#pragma unroll
            for (int q = 0; q < 8; q++) {
                const float4 k4 = krow4[q];
                const float2 p0 = vqw[4 * q + 0];
                const float2 p1 = vqw[4 * q + 1];
                const float2 p2 = vqw[4 * q + 2];
                const float2 p3 = vqw[4 * q + 3];
                e = fmaf(p0.y, tanh_fast(p0.x + k4.x), e);
                e = fmaf(p1.y, tanh_fast(p1.x + k4.y), e);
                e = fmaf(p2.y, tanh_fast(p2.x + k4.z), e);
                e = fmaf(p3.y, tanh_fast(p3.x + k4.w), e);
            }
            ssum += __expf(e - S);

            const float* orow = os + (c * 32) * KSTR + lane;
#pragma unroll
            for (int jj = 0; jj < 32; jj++) {
                float ej = __shfl_sync(0xffffffffu, e, jj);
                ctx = fmaf(ej, orow[jj * KSTR], ctx);
            }
        }
#pragma unroll
        for (int s = 16; s > 0; s >>= 1)
            ssum += __shfl_xor_sync(0xffffffffu, ssum, s);
        if (tail > 0) ssum += (float)tail * __expf(ep - S);

        const int base = (b * 2 + half) * LEN + i;
        g_pc[base * HDIM + lane] = ctx;
        if (lane == 0) g_ps[base] = ssum;
    }
}

// ---------------------------------------------------------------------------
// K4b: combiner: lse, ctx = c0+c1-lse*osum, fc head. One warp per i-row.
// ---------------------------------------------------------------------------
__global__ __launch_bounds__(256) void attn2_kernel(
    const float* __restrict__ v,
    const float* __restrict__ fc_w,
    const float* __restrict__ fc_b,
    float* __restrict__ y)
{
    __shared__ float fcw[ODIM][33];
    __shared__ float fcbs[16];
    __shared__ float cx[8][33];

    const int tid = threadIdx.x;
    const int wid = tid >> 5, lane = tid & 31;

    for (int idx = tid; idx < ODIM * HDIM; idx += 256) {
        int o = idx / HDIM, h = idx % HDIM;
        fcw[o][h] = fc_w[idx];
    }
    if (tid < ODIM) fcbs[tid] = fc_b[tid];

    float S = fabsf(v[lane]);
#pragma unroll
    for (int s = 16; s > 0; s >>= 1)
        S += __shfl_xor_sync(0xffffffffu, S, s);
    __syncthreads();

    const int r = blockIdx.x * 8 + wid;     // global row in [0, 8192)
    const int b = r >> 9, i = r & 511;
    const int base0 = (b * 2 + 0) * LEN + i;
    const int base1 = (b * 2 + 1) * LEN + i;

    const float ssum = g_ps[base0] + g_ps[base1];
    const float lse  = S + __logf(ssum);
    const float osv  = g_osum[(b * 2 + 0) * HDIM + lane] +
                       g_osum[(b * 2 + 1) * HDIM + lane];
    float ctx = g_pc[base0 * HDIM + lane] + g_pc[base1 * HDIM + lane]
              - lse * osv;

    cx[wid][lane] = ctx;
    __syncwarp();
    if (lane < ODIM) {
        float acc = fcbs[lane];
#pragma unroll
        for (int h = 0; h < HDIM; h++)
            acc = fmaf(fcw[lane][h], cx[wid][h], acc);
        y[(size_t)r * ODIM + lane] = acc;
    }
}

// ---------------------------------------------------------------------------
extern "C" void kernel_launch(void* const* d_in, const int* in_sizes, int n_in,
                              void* d_out, int out_size)
{
    const float* x      = (const float*)d_in[0];
    const int*   x_lens = (const int*)  d_in[1];
    const float* h0     = (const float*)d_in[2];
    const float* w_ih   = (const float*)d_in[3];
    const float* w_hh   = (const float*)d_in[4];
    const float* b_ih   = (const float*)d_in[5];
    const float* b_hh   = (const float*)d_in[6];
    const float* fc_w   = (const float*)d_in[7];
    const float* fc_b   = (const float*)d_in[8];
    const float* fch_w  = (const float*)d_in[9];
    const float* fco_w  = (const float*)d_in[10];
    const float* v      = (const float*)d_in[11];
    float* y = (float*)d_out;

    const size_t a1_smem = (size_t)(2 * JH * KSTR + 32 + 16 * 33 + 8 +
                                    16 * 33 * 2 + 16) * sizeof(float);
    cudaFuncSetAttribute(attn1_kernel,
                         cudaFuncAttributeMaxDynamicSharedMemorySize,
                         (int)a1_smem);

    gx_kernel <<<(BATCH * LEN) / 64, 256>>>(x, w_ih, b_ih);
    gru_kernel<<<BATCH, 32>>>(w_hh, b_hh, h0, x_lens);
    qk_kernel <<<(BATCH * LEN) / 8, 256>>>(fch_w, fco_w);
    attn1_kernel<<<dim3(LEN / TI2, 2, BATCH), 512, a1_smem>>>(v, x_lens);
    attn2_kernel<<<(BATCH * LEN) / 8, 256>>>(v, fc_w, fc_b, y);
}

// round 9
// speedup vs baseline: 1.1367x; 1.1367x over previous
#include <cuda_runtime.h>

#define BATCH 16
#define LEN   512
#define IDIM  300
#define HDIM  32
#define ODIM  15
#define GDIM  96
#define TI2   32          // i-rows per attn1 block
#define KSTR  36          // smem row stride (floats), 16B-aligned
#define ASTR  68          // attn2 e-tile stride (floats), 16B-aligned

typedef unsigned long long ull;

// Scratch as float4 arrays (guarantees 16B alignment for vector access)
__device__ float4 g_gx4 [BATCH * LEN * GDIM / 4];
__device__ float4 g_out4[BATCH * LEN * HDIM / 4];
__device__ float4 g_qh4 [BATCH * LEN * HDIM / 4];
__device__ float4 g_kh4 [BATCH * LEN * HDIM / 4];
#define g_gx  ((float*)g_gx4)
#define g_out ((float*)g_out4)
#define g_qh  ((float*)g_qh4)
#define g_kh  ((float*)g_kh4)

__device__ float4 g_e4[BATCH * LEN * LEN / 4];       // raw e scores
#define g_e ((float*)g_e4)
__device__ float g_ps[BATCH * LEN];                   // per-row sum exp(e-S)

__device__ __forceinline__ float tanh_fast(float x) {
    float y;
    asm("tanh.approx.f32 %0, %1;" : "=f"(y) : "f"(x));
    return y;
}
__device__ __forceinline__ ull ffma2u(ull a, ull b, ull c) {
    ull d;
    asm("fma.rn.f32x2 %0, %1, %2, %3;" : "=l"(d) : "l"(a), "l"(b), "l"(c));
    return d;
}
__device__ __forceinline__ ull add2u(ull a, ull b) {
    ull d;
    asm("add.rn.f32x2 %0, %1, %2;" : "=l"(d) : "l"(a), "l"(b));
    return d;
}
__device__ __forceinline__ ull pack2(float lo, float hi) {
    ull d;
    asm("mov.b64 %0, {%1, %2};" : "=l"(d) : "f"(lo), "f"(hi));
    return d;
}
__device__ __forceinline__ float hsum2(ull a) {
    float lo, hi;
    asm("mov.b64 {%0, %1}, %2;" : "=f"(lo), "=f"(hi) : "l"(a));
    return lo + hi;
}

// ---------------------------------------------------------------------------
// K1: gx = x @ w_ih^T + b_ih   (M=8192, N=96, K=300)
// ---------------------------------------------------------------------------
__global__ __launch_bounds__(256) void gx_kernel(
    const float* __restrict__ x,
    const float* __restrict__ w_ih,
    const float* __restrict__ b_ih)
{
    __shared__ float xs[16][65];
    __shared__ float ws[16][97];

    const int m0 = blockIdx.x * 64;
    const int tx = threadIdx.x & 15;
    const int ty = threadIdx.x >> 4;

    float acc[4][6];
#pragma unroll
    for (int i = 0; i < 4; i++)
#pragma unroll
        for (int j = 0; j < 6; j++) acc[i][j] = 0.f;

    for (int kt = 0; kt < IDIM; kt += 16) {
        for (int idx = threadIdx.x; idx < 64 * 16; idx += 256) {
            int r = idx >> 4, kk = idx & 15;
            int k = kt + kk;
            xs[kk][r] = (k < IDIM) ? x[(m0 + r) * IDIM + k] : 0.f;
        }
        for (int idx = threadIdx.x; idx < 96 * 16; idx += 256) {
            int c = idx >> 4, kk = idx & 15;
            int k = kt + kk;
            ws[kk][c] = (k < IDIM) ? w_ih[c * IDIM + k] : 0.f;
        }
        __syncthreads();
#pragma unroll
        for (int kk = 0; kk < 16; kk++) {
            float xv[4], wv[6];
#pragma unroll
            for (int i = 0; i < 4; i++) xv[i] = xs[kk][ty * 4 + i];
#pragma unroll
            for (int j = 0; j < 6; j++) wv[j] = ws[kk][tx * 6 + j];
#pragma unroll
            for (int i = 0; i < 4; i++)
#pragma unroll
                for (int j = 0; j < 6; j++)
                    acc[i][j] = fmaf(xv[i], wv[j], acc[i][j]);
        }
        __syncthreads();
    }
#pragma unroll
    for (int i = 0; i < 4; i++) {
        int m = m0 + ty * 4 + i;
#pragma unroll
        for (int j = 0; j < 6; j++) {
            int c = tx * 6 + j;
            g_gx[m * GDIM + c] = acc[i][j] + b_ih[c];
        }
    }
}

// ---------------------------------------------------------------------------
// K2: GRU recurrence (R7 proven version: packed-pair shfl, depth-4 prefetch)
// ---------------------------------------------------------------------------
__global__ __launch_bounds__(32) void gru_kernel(
    const float* __restrict__ w_hh,
    const float* __restrict__ b_hh,
    const float* __restrict__ h0,
    const int*   __restrict__ x_lens)
{
    const int b = blockIdx.x;
    const int h = threadIdx.x;

    const ull* w8 = (const ull*)w_hh;   // [96][16] packed pairs
    ull wr2[16], wz2[16], wn2[16];
#pragma unroll
    for (int k = 0; k < 16; k++) {
        wr2[k] = w8[(0 * HDIM + h) * 16 + k];
        wz2[k] = w8[(1 * HDIM + h) * 16 + k];
        wn2[k] = w8[(2 * HDIM + h) * 16 + k];
    }
    const ull brp = pack2(b_hh[h], 0.f);
    const ull bzp = pack2(b_hh[HDIM + h], 0.f);
    const ull bnp = pack2(b_hh[2 * HDIM + h], 0.f);

    float hcur = h0[b * HDIM + h];
    float nb0 = __shfl_xor_sync(0xffffffffu, hcur, 1);
    ull hpair = (h & 1) ? pack2(nb0, hcur) : pack2(hcur, nb0);

    const int len = x_lens[b];
    const float* gxb = g_gx + (size_t)b * LEN * GDIM;
    float* outb = g_out + (size_t)b * LEN * HDIM;

    float rxb[4], zxb[4], nxb[4];
#pragma unroll
    for (int t = 0; t < 4; t++) {
        const float* p = gxb + t * GDIM;
        rxb[t] = p[h]; zxb[t] = p[HDIM + h]; nxb[t] = p[2 * HDIM + h];
    }

#pragma unroll 4
    for (int t = 0; t < LEN; t++) {
        const int s = t & 3;
        const float rx = rxb[s], zx = zxb[s], nx = nxb[s];
        if (t + 4 < LEN) {
            const float* p = gxb + (t + 4) * GDIM;
            rxb[s] = p[h]; zxb[s] = p[HDIM + h]; nxb[s] = p[2 * HDIM + h];
        }

        ull ra[4] = {brp, 0ull, 0ull, 0ull};
        ull za[4] = {bzp, 0ull, 0ull, 0ull};
        ull na[4] = {bnp, 0ull, 0ull, 0ull};
#pragma unroll
        for (int k = 0; k < 16; k++) {
            const ull h2 = __shfl_sync(0xffffffffu, hpair, 2 * k);
            const int p = k & 3;
            ra[p] = ffma2u(wr2[k], h2, ra[p]);
            za[p] = ffma2u(wz2[k], h2, za[p]);
            na[p] = ffma2u(wn2[k], h2, na[p]);
        }
        const float rh = hsum2(add2u(add2u(ra[0], ra[1]), add2u(ra[2], ra[3])));
        const float zh = hsum2(add2u(add2u(za[0], za[1]), add2u(za[2], za[3])));
        const float nh = hsum2(add2u(add2u(na[0], na[1]), add2u(na[2], na[3])));

        const float r = fmaf(tanh_fast((rx + rh) * 0.5f), 0.5f, 0.5f);
        const float z = fmaf(tanh_fast((zx + zh) * 0.5f), 0.5f, 0.5f);
        const float n = tanh_fast(fmaf(r, nh, nx));
        hcur = fmaf(z, hcur - n, n);

        const float nb = __shfl_xor_sync(0xffffffffu, hcur, 1);
        hpair = (h & 1) ? pack2(nb, hcur) : pack2(hcur, nb);

        outb[t * HDIM + h] = (t < len) ? hcur : 0.f;
    }
}

// ---------------------------------------------------------------------------
// K3: qh = out@fch_w^T, kh = out@fco_w^T
// ---------------------------------------------------------------------------
__global__ __launch_bounds__(256) void qk_kernel(
    const float* __restrict__ fch_w,
    const float* __restrict__ fco_w)
{
    __shared__ float wq[HDIM][HDIM + 1];
    __shared__ float wk[HDIM][HDIM + 1];
    __shared__ float os[8][HDIM];

    const int tid = threadIdx.x;
    for (int idx = tid; idx < HDIM * HDIM; idx += 256) {
        int c = idx >> 5, k = idx & 31;
        wq[k][c] = fch_w[c * HDIM + k];
        wk[k][c] = fco_w[c * HDIM + k];
    }
    const int m0 = blockIdx.x * 8;
    const int r = tid >> 5, c = tid & 31;
    os[r][c] = g_out[(m0 + r) * HDIM + c];
    __syncthreads();

    float aq = 0.f, ak = 0.f;
#pragma unroll
    for (int k = 0; k < HDIM; k++) {
        float o = os[r][k];
        aq = fmaf(o, wq[k][c], aq);
        ak = fmaf(o, wk[k][c], ak);
    }
    g_qh[(m0 + r) * HDIM + c] = aq;
    g_kh[(m0 + r) * HDIM + c] = ak;
}

// ---------------------------------------------------------------------------
// K4a: e scores + row exp-sums. One warp per i-row (2 per warp via ii loop).
// Full key tile (512 rows) in smem; q,v in registers (R7-style).
// ---------------------------------------------------------------------------
__global__ __launch_bounds__(512) void attn1_kernel(
    const float* __restrict__ v,
    const int*   __restrict__ x_lens)
{
    extern __shared__ float sm[];
    float* ks  = sm;                   // [512][36]
    float* vsh = ks + LEN * KSTR;      // 32

    const int b   = blockIdx.y;
    const int i0  = blockIdx.x * TI2;
    const int tid = threadIdx.x;
    const int wid = tid >> 5, lane = tid & 31;

    for (int idx = tid; idx < LEN * 8; idx += 512) {
        int j = idx >> 3, q = idx & 7;
        *(float4*)(ks + j * KSTR + q * 4) = g_kh4[(b * LEN + j) * 8 + q];
    }
    if (tid < HDIM) vsh[tid] = v[tid];
    __syncthreads();

    const int len    = x_lens[b];
    const int chunks = (len + 31) >> 5;          // 8..16
    const int tailc  = (LEN >> 5) - chunks;      // fully-padded chunks
    const int tail   = tailc * 32;

    const float vl = vsh[lane];
    float S = fabsf(vl);
#pragma unroll
    for (int s = 16; s > 0; s >>= 1)
        S += __shfl_xor_sync(0xffffffffu, S, s);

    float vr[HDIM];
#pragma unroll
    for (int h = 0; h < HDIM; h++) vr[h] = vsh[h];

    for (int ii = wid; ii < TI2; ii += 16) {
        const int i = i0 + ii;
        const size_t row = (size_t)b * LEN + i;

        union { float4 v4[8]; float f[HDIM]; } qu;
#pragma unroll
        for (int q = 0; q < 8; q++)
            qu.v4[q] = g_qh4[row * 8 + q];

        // e_pad = sum_h v_h * tanh(q_h)
        float ep = vl * tanh_fast(qu.f[lane & 31]);
        // note: qu.f[lane] must be lane's own q value; use shfl-safe path:
        ep = vl * tanh_fast(__shfl_sync(0xffffffffu,
                 qu.f[0], 0));  // placeholder overwritten below
        // compute ep robustly: lane h uses q_h from its own copy (identical)
        ep = vl * tanh_fast(qu.f[31] * 0.f + qu.f[0] * 0.f +
                            0.f);  // will be replaced
        // -- simple correct version: every lane has full qu; use its lane idx
        {
            float qh_lane = 0.f;
#pragma unroll
            for (int h = 0; h < HDIM; h++)
                if (h == lane) qh_lane = qu.f[h];
            ep = vl * tanh_fast(qh_lane);
        }
#pragma unroll
        for (int s = 16; s > 0; s >>= 1)
            ep += __shfl_xor_sync(0xffffffffu, ep, s);

        float* erow = g_e + row * LEN;
        float ssum = 0.f;
        for (int c = 0; c < chunks; c++) {
            const float4* krow4 = (const float4*)(ks + (c * 32 + lane) * KSTR);
            float e = 0.f;
#pragma unroll
            for (int q = 0; q < 8; q++) {
                const float4 k4 = krow4[q];
                e = fmaf(vr[4 * q + 0], tanh_fast(qu.f[4 * q + 0] + k4.x), e);
                e = fmaf(vr[4 * q + 1], tanh_fast(qu.f[4 * q + 1] + k4.y), e);
                e = fmaf(vr[4 * q + 2], tanh_fast(qu.f[4 * q + 2] + k4.z), e);
                e = fmaf(vr[4 * q + 3], tanh_fast(qu.f[4 * q + 3] + k4.w), e);
            }
            ssum += __expf(e - S);
            erow[c * 32 + lane] = e;
        }
        // padded chunks: e = ep (store only)
        for (int c = chunks; c < (LEN >> 5); c++)
            erow[c * 32 + lane] = ep;

#pragma unroll
        for (int s = 16; s > 0; s >>= 1)
            ssum += __shfl_xor_sync(0xffffffffu, ssum, s);
        if (tail > 0) ssum += (float)tail * __expf(ep - S);
        if (lane == 0) g_ps[row] = ssum;
    }
}

// ---------------------------------------------------------------------------
// K4b: ctx GEMM (64i x 32h per block, 8 j-tiles of 64) + epilogue
// ctx = e@out - lse*osum, then fc head.
// ---------------------------------------------------------------------------
__global__ __launch_bounds__(256) void attn2_kernel(
    const float* __restrict__ v,
    const float* __restrict__ fc_w,
    const float* __restrict__ fc_b,
    float* __restrict__ y)
{
    __shared__ float As[64 * ASTR];       // e tile TRANSPOSED: As[j][i]
    __shared__ float Bs[64 * KSTR];       // out tile: Bs[j][h]
    __shared__ float osr[8][33];          // osum warp partials
    __shared__ float osum_s[32];
    __shared__ float cxs[64][33];
    __shared__ float fcw[ODIM][33];
    __shared__ float fcbs[16];

    const int b   = blockIdx.y;
    const int i0  = blockIdx.x * 64;
    const int tid = threadIdx.x;
    const int tx  = tid & 31;             // h
    const int ty  = tid >> 5;             // 0..7

    for (int idx = tid; idx < ODIM * HDIM; idx += 256) {
        int o = idx / HDIM, h = idx % HDIM;
        fcw[o][h] = fc_w[idx];
    }
    if (tid < ODIM) fcbs[tid] = fc_b[tid];

    float S = fabsf(v[tx]);
#pragma unroll
    for (int s = 16; s > 0; s >>= 1)
        S += __shfl_xor_sync(0xffffffffu, S, s);

    float acc[8];
#pragma unroll
    for (int k = 0; k < 8; k++) acc[k] = 0.f;
    float posum = 0.f;

    for (int jt = 0; jt < 8; jt++) {
        const int j0 = jt * 64;
        // load e tile transposed: As[j][i] <- e[b][i0+i][j0+j]
        for (int idx = tid; idx < 64 * 16; idx += 256) {
            int i = idx >> 4, q = idx & 15;
            float4 ev = g_e4[(((size_t)b * LEN + i0 + i) * LEN + j0) / 4 + q];
            As[(q * 4 + 0) * ASTR + i] = ev.x;
            As[(q * 4 + 1) * ASTR + i] = ev.y;
            As[(q * 4 + 2) * ASTR + i] = ev.z;
            As[(q * 4 + 3) * ASTR + i] = ev.w;
        }
        // load out tile: Bs[j][h]
        for (int idx = tid; idx < 64 * 8; idx += 256) {
            int j = idx >> 3, q = idx & 7;
            *(float4*)(Bs + j * KSTR + q * 4) =
                g_out4[((size_t)b * LEN + j0 + j) * 8 + q];
        }
        __syncthreads();

        // osum partial: warp ty sums rows ty*8..ty*8+7, lane = h
#pragma unroll
        for (int r = 0; r < 8; r++)
            posum += Bs[(ty * 8 + r) * KSTR + tx];

        // GEMM: thread computes i = ty*8..ty*8+7, h = tx
#pragma unroll 4
        for (int jj = 0; jj < 64; jj++) {
            const float bv = Bs[jj * KSTR + tx];
            const float4 a0 = *(const float4*)(As + jj * ASTR + ty * 8);
            const float4 a1 = *(const float4*)(As + jj * ASTR + ty * 8 + 4);
            acc[0] = fmaf(a0.x, bv, acc[0]);
            acc[1] = fmaf(a0.y, bv, acc[1]);
            acc[2] = fmaf(a0.z, bv, acc[2]);
            acc[3] = fmaf(a0.w, bv, acc[3]);
            acc[4] = fmaf(a1.x, bv, acc[4]);
            acc[5] = fmaf(a1.y, bv, acc[5]);
            acc[6] = fmaf(a1.z, bv, acc[6]);
            acc[7] = fmaf(a1.w, bv, acc[7]);
        }
        __syncthreads();
    }

    // reduce osum partials
    osr[ty][tx] = posum;
    __syncthreads();
    if (tid < HDIM) {
        float t = 0.f;
#pragma unroll
        for (int w = 0; w < 8; w++) t += osr[w][tid];
        osum_s[tid] = t;
    }
    __syncthreads();

    // epilogue: ctx -= lse * osum; stage to smem
    const float osv = osum_s[tx];
#pragma unroll
    for (int k = 0; k < 8; k++) {
        const int i = ty * 8 + k;
        const float lse = S + __logf(g_ps[(size_t)b * LEN + i0 + i]);
        cxs[i][tx] = fmaf(-lse, osv, acc[k]);
    }
    __syncthreads();

    // fc head: 64 x 15 outputs
    for (int idx = tid; idx < 64 * ODIM; idx += 256) {
        const int i2 = idx / ODIM, o = idx % ODIM;
        float r = fcbs[o];
#pragma unroll
        for (int h = 0; h < HDIM; h++)
            r = fmaf(fcw[o][h], cxs[i2][h], r);
        y[((size_t)b * LEN + i0 + i2) * ODIM + o] = r;
    }
}

// ---------------------------------------------------------------------------
extern "C" void kernel_launch(void* const* d_in, const int* in_sizes, int n_in,
                              void* d_out, int out_size)
{
    const float* x      = (const float*)d_in[0];
    const int*   x_lens = (const int*)  d_in[1];
    const float* h0     = (const float*)d_in[2];
    const float* w_ih   = (const float*)d_in[3];
    const float* w_hh   = (const float*)d_in[4];
    const float* b_ih   = (const float*)d_in[5];
    const float* b_hh   = (const float*)d_in[6];
    const float* fc_w   = (const float*)d_in[7];
    const float* fc_b   = (const float*)d_in[8];
    const float* fch_w  = (const float*)d_in[9];
    const float* fco_w  = (const float*)d_in[10];
    const float* v      = (const float*)d_in[11];
    float* y = (float*)d_out;

    const size_t a1_smem = (size_t)(LEN * KSTR + 32 + 16) * sizeof(float);
    cudaFuncSetAttribute(attn1_kernel,
                         cudaFuncAttributeMaxDynamicSharedMemorySize,
                         (int)a1_smem);

    gx_kernel <<<(BATCH * LEN) / 64, 256>>>(x, w_ih, b_ih);
    gru_kernel<<<BATCH, 32>>>(w_hh, b_hh, h0, x_lens);
    qk_kernel <<<(BATCH * LEN) / 8, 256>>>(fch_w, fco_w);
    attn1_kernel<<<dim3(LEN / TI2, BATCH), 512, a1_smem>>>(v, x_lens);
    attn2_kernel<<<dim3(LEN / 64, BATCH), 256>>>(v, fc_w, fc_b, y);
}

// round 10
// speedup vs baseline: 1.1696x; 1.0290x over previous
#include <cuda_runtime.h>

#define BATCH 16
#define LEN   512
#define IDIM  300
#define HDIM  32
#define ODIM  15
#define GDIM  96
#define JH    256         // keys per attn1 block (half)
#define TI1   16          // i-rows per attn1 block
#define KSTR  36          // smem row stride (floats), 16B-aligned
#define ESTR  65          // attn2 e-tile stride (odd -> conflict-free columns)

typedef unsigned long long ull;

// Scratch as float4 arrays (guarantees 16B alignment for vector access)
__device__ float4 g_gx4 [BATCH * LEN * GDIM / 4];
__device__ float4 g_out4[BATCH * LEN * HDIM / 4];
__device__ float4 g_qh4 [BATCH * LEN * HDIM / 4];
__device__ float4 g_kh4 [BATCH * LEN * HDIM / 4];
#define g_gx  ((float*)g_gx4)
#define g_out ((float*)g_out4)
#define g_qh  ((float*)g_qh4)
#define g_kh  ((float*)g_kh4)

__device__ float4 g_e4[BATCH * LEN * LEN / 4];       // raw e scores
#define g_e ((float*)g_e4)
__device__ float g_ps[BATCH * 2 * LEN];               // per-(row,half) sum exp(e-S)

__device__ __forceinline__ float tanh_fast(float x) {
    float y;
    asm("tanh.approx.f32 %0, %1;" : "=f"(y) : "f"(x));
    return y;
}
__device__ __forceinline__ ull ffma2u(ull a, ull b, ull c) {
    ull d;
    asm("fma.rn.f32x2 %0, %1, %2, %3;" : "=l"(d) : "l"(a), "l"(b), "l"(c));
    return d;
}
__device__ __forceinline__ ull add2u(ull a, ull b) {
    ull d;
    asm("add.rn.f32x2 %0, %1, %2;" : "=l"(d) : "l"(a), "l"(b));
    return d;
}
__device__ __forceinline__ ull pack2(float lo, float hi) {
    ull d;
    asm("mov.b64 %0, {%1, %2};" : "=l"(d) : "f"(lo), "f"(hi));
    return d;
}
__device__ __forceinline__ float hsum2(ull a) {
    float lo, hi;
    asm("mov.b64 {%0, %1}, %2;" : "=f"(lo), "=f"(hi) : "l"(a));
    return lo + hi;
}

// ---------------------------------------------------------------------------
// K1: gx = x @ w_ih^T + b_ih   (M=8192, N=96, K=300)
// ---------------------------------------------------------------------------
__global__ __launch_bounds__(256) void gx_kernel(
    const float* __restrict__ x,
    const float* __restrict__ w_ih,
    const float* __restrict__ b_ih)
{
    __shared__ float xs[16][65];
    __shared__ float ws[16][97];

    const int m0 = blockIdx.x * 64;
    const int tx = threadIdx.x & 15;
    const int ty = threadIdx.x >> 4;

    float acc[4][6];
#pragma unroll
    for (int i = 0; i < 4; i++)
#pragma unroll
        for (int j = 0; j < 6; j++) acc[i][j] = 0.f;

    for (int kt = 0; kt < IDIM; kt += 16) {
        for (int idx = threadIdx.x; idx < 64 * 16; idx += 256) {
            int r = idx >> 4, kk = idx & 15;
            int k = kt + kk;
            xs[kk][r] = (k < IDIM) ? x[(m0 + r) * IDIM + k] : 0.f;
        }
        for (int idx = threadIdx.x; idx < 96 * 16; idx += 256) {
            int c = idx >> 4, kk = idx & 15;
            int k = kt + kk;
            ws[kk][c] = (k < IDIM) ? w_ih[c * IDIM + k] : 0.f;
        }
        __syncthreads();
#pragma unroll
        for (int kk = 0; kk < 16; kk++) {
            float xv[4], wv[6];
#pragma unroll
            for (int i = 0; i < 4; i++) xv[i] = xs[kk][ty * 4 + i];
#pragma unroll
            for (int j = 0; j < 6; j++) wv[j] = ws[kk][tx * 6 + j];
#pragma unroll
            for (int i = 0; i < 4; i++)
#pragma unroll
                for (int j = 0; j < 6; j++)
                    acc[i][j] = fmaf(xv[i], wv[j], acc[i][j]);
        }
        __syncthreads();
    }
#pragma unroll
    for (int i = 0; i < 4; i++) {
        int m = m0 + ty * 4 + i;
#pragma unroll
        for (int j = 0; j < 6; j++) {
            int c = tx * 6 + j;
            g_gx[m * GDIM + c] = acc[i][j] + b_ih[c];
        }
    }
}

// ---------------------------------------------------------------------------
// K2: GRU recurrence (proven R7 version)
// ---------------------------------------------------------------------------
__global__ __launch_bounds__(32) void gru_kernel(
    const float* __restrict__ w_hh,
    const float* __restrict__ b_hh,
    const float* __restrict__ h0,
    const int*   __restrict__ x_lens)
{
    const int b = blockIdx.x;
    const int h = threadIdx.x;

    const ull* w8 = (const ull*)w_hh;   // [96][16] packed pairs
    ull wr2[16], wz2[16], wn2[16];
#pragma unroll
    for (int k = 0; k < 16; k++) {
        wr2[k] = w8[(0 * HDIM + h) * 16 + k];
        wz2[k] = w8[(1 * HDIM + h) * 16 + k];
        wn2[k] = w8[(2 * HDIM + h) * 16 + k];
    }
    const ull brp = pack2(b_hh[h], 0.f);
    const ull bzp = pack2(b_hh[HDIM + h], 0.f);
    const ull bnp = pack2(b_hh[2 * HDIM + h], 0.f);

    float hcur = h0[b * HDIM + h];
    float nb0 = __shfl_xor_sync(0xffffffffu, hcur, 1);
    ull hpair = (h & 1) ? pack2(nb0, hcur) : pack2(hcur, nb0);

    const int len = x_lens[b];
    const float* gxb = g_gx + (size_t)b * LEN * GDIM;
    float* outb = g_out + (size_t)b * LEN * HDIM;

    float rxb[4], zxb[4], nxb[4];
#pragma unroll
    for (int t = 0; t < 4; t++) {
        const float* p = gxb + t * GDIM;
        rxb[t] = p[h]; zxb[t] = p[HDIM + h]; nxb[t] = p[2 * HDIM + h];
    }

#pragma unroll 4
    for (int t = 0; t < LEN; t++) {
        const int s = t & 3;
        const float rx = rxb[s], zx = zxb[s], nx = nxb[s];
        if (t + 4 < LEN) {
            const float* p = gxb + (t + 4) * GDIM;
            rxb[s] = p[h]; zxb[s] = p[HDIM + h]; nxb[s] = p[2 * HDIM + h];
        }

        ull ra[4] = {brp, 0ull, 0ull, 0ull};
        ull za[4] = {bzp, 0ull, 0ull, 0ull};
        ull na[4] = {bnp, 0ull, 0ull, 0ull};
#pragma unroll
        for (int k = 0; k < 16; k++) {
            const ull h2 = __shfl_sync(0xffffffffu, hpair, 2 * k);
            const int p = k & 3;
            ra[p] = ffma2u(wr2[k], h2, ra[p]);
            za[p] = ffma2u(wz2[k], h2, za[p]);
            na[p] = ffma2u(wn2[k], h2, na[p]);
        }
        const float rh = hsum2(add2u(add2u(ra[0], ra[1]), add2u(ra[2], ra[3])));
        const float zh = hsum2(add2u(add2u(za[0], za[1]), add2u(za[2], za[3])));
        const float nh = hsum2(add2u(add2u(na[0], na[1]), add2u(na[2], na[3])));

        const float r = fmaf(tanh_fast((rx + rh) * 0.5f), 0.5f, 0.5f);
        const float z = fmaf(tanh_fast((zx + zh) * 0.5f), 0.5f, 0.5f);
        const float n = tanh_fast(fmaf(r, nh, nx));
        hcur = fmaf(z, hcur - n, n);

        const float nb = __shfl_xor_sync(0xffffffffu, hcur, 1);
        hpair = (h & 1) ? pack2(nb, hcur) : pack2(hcur, nb);

        outb[t * HDIM + h] = (t < len) ? hcur : 0.f;
    }
}

// ---------------------------------------------------------------------------
// K3: qh = out@fch_w^T, kh = out@fco_w^T
// ---------------------------------------------------------------------------
__global__ __launch_bounds__(256) void qk_kernel(
    const float* __restrict__ fch_w,
    const float* __restrict__ fco_w)
{
    __shared__ float wq[HDIM][HDIM + 1];
    __shared__ float wk[HDIM][HDIM + 1];
    __shared__ float os[8][HDIM];

    const int tid = threadIdx.x;
    for (int idx = tid; idx < HDIM * HDIM; idx += 256) {
        int c = idx >> 5, k = idx & 31;
        wq[k][c] = fch_w[c * HDIM + k];
        wk[k][c] = fco_w[c * HDIM + k];
    }
    const int m0 = blockIdx.x * 8;
    const int r = tid >> 5, c = tid & 31;
    os[r][c] = g_out[(m0 + r) * HDIM + c];
    __syncthreads();

    float aq = 0.f, ak = 0.f;
#pragma unroll
    for (int k = 0; k < HDIM; k++) {
        float o = os[r][k];
        aq = fmaf(o, wq[k][c], aq);
        ak = fmaf(o, wk[k][c], ak);
    }
    g_qh[(m0 + r) * HDIM + c] = aq;
    g_kh[(m0 + r) * HDIM + c] = ak;
}

// ---------------------------------------------------------------------------
// K4a: e scores + per-half exp-sums. 256 threads, half-sized key tile (37KB),
// v from smem broadcast -> low regs -> 4 blocks/SM.
// ---------------------------------------------------------------------------
__global__ __launch_bounds__(256, 4) void attn1_kernel(
    const float* __restrict__ v,
    const int*   __restrict__ x_lens)
{
    __shared__ float ks[JH * KSTR];
    __shared__ float vsh[HDIM];

    const int b    = blockIdx.z;
    const int half = blockIdx.y;
    const int i0   = blockIdx.x * TI1;
    const int tid  = threadIdx.x;
    const int wid  = tid >> 5, lane = tid & 31;
    const int jbase = b * LEN + half * JH;

    for (int idx = tid; idx < JH * 8; idx += 256) {
        int j = idx >> 3, q = idx & 7;
        *(float4*)(ks + j * KSTR + q * 4) = g_kh4[(jbase + j) * 8 + q];
    }
    if (tid < HDIM) vsh[tid] = v[tid];
    __syncthreads();

    const int len    = x_lens[b];                     // 256..512
    const int kcount = half ? (len - JH) : JH;        // valid keys this half
    const int chunks = (kcount + 31) >> 5;            // 0..8
    const int tail   = JH - chunks * 32;

    const float vl = vsh[lane];
    float S = fabsf(vl);
#pragma unroll
    for (int s = 16; s > 0; s >>= 1)
        S += __shfl_xor_sync(0xffffffffu, S, s);

    for (int ii = wid; ii < TI1; ii += 8) {
        const int i = i0 + ii;
        const size_t row = (size_t)b * LEN + i;

        union { float4 v4[8]; float f[HDIM]; } qu;
#pragma unroll
        for (int q = 0; q < 8; q++)
            qu.v4[q] = g_qh4[row * 8 + q];

        float ep = 0.f;
        if (tail > 0) {
            ep = vl * tanh_fast(g_qh[row * HDIM + lane]);
#pragma unroll
            for (int s = 16; s > 0; s >>= 1)
                ep += __shfl_xor_sync(0xffffffffu, ep, s);
        }

        float* erow = g_e + row * LEN + half * JH;
        float ssum = 0.f;
        for (int c = 0; c < chunks; c++) {
            const float4* krow4 = (const float4*)(ks + (c * 32 + lane) * KSTR);
            float e = 0.f;
#pragma unroll
            for (int q = 0; q < 8; q++) {
                const float4 k4 = krow4[q];
                e = fmaf(vsh[4 * q + 0], tanh_fast(qu.f[4 * q + 0] + k4.x), e);
                e = fmaf(vsh[4 * q + 1], tanh_fast(qu.f[4 * q + 1] + k4.y), e);
                e = fmaf(vsh[4 * q + 2], tanh_fast(qu.f[4 * q + 2] + k4.z), e);
                e = fmaf(vsh[4 * q + 3], tanh_fast(qu.f[4 * q + 3] + k4.w), e);
            }
            ssum += __expf(e - S);
            erow[c * 32 + lane] = e;
        }
        for (int c = chunks; c < JH / 32; c++)
            erow[c * 32 + lane] = ep;

#pragma unroll
        for (int s = 16; s > 0; s >>= 1)
            ssum += __shfl_xor_sync(0xffffffffu, ssum, s);
        if (tail > 0) ssum += (float)tail * __expf(ep - S);
        if (lane == 0) g_ps[(b * 2 + half) * LEN + i] = ssum;
    }
}

// ---------------------------------------------------------------------------
// K4b: ctx GEMM (32i x 32h per block, 8 j-tiles of 64), conflict-free smem,
// epilogue ctx = e@out - lse*osum, then fc head.
// warp w owns h-group w*4..w*4+3; lane = local i.
// ---------------------------------------------------------------------------
__global__ __launch_bounds__(256) void attn2_kernel(
    const float* __restrict__ v,
    const float* __restrict__ fc_w,
    const float* __restrict__ fc_b,
    float* __restrict__ y)
{
    __shared__ float As[32 * ESTR];       // e tile, row-major [i][j], stride 65
    __shared__ float Bs[64 * KSTR];       // out tile [j][h]
    __shared__ float osum_s[32];
    __shared__ float cxs[32][33];
    __shared__ float fcw[ODIM][33];
    __shared__ float fcbs[16];

    const int b   = blockIdx.y;
    const int i0  = blockIdx.x * 32;
    const int tid = threadIdx.x;
    const int w   = tid >> 5;             // warp: h-group
    const int lane = tid & 31;            // local i
    const int w4  = w * 4;

    for (int idx = tid; idx < ODIM * HDIM; idx += 256) {
        int o = idx / HDIM, h = idx % HDIM;
        fcw[o][h] = fc_w[idx];
    }
    if (tid < ODIM) fcbs[tid] = fc_b[tid];

    float S = fabsf(v[lane]);
#pragma unroll
    for (int s = 16; s > 0; s >>= 1)
        S += __shfl_xor_sync(0xffffffffu, S, s);

    float acc[4] = {0.f, 0.f, 0.f, 0.f};
    float posum[4] = {0.f, 0.f, 0.f, 0.f};

    for (int jt = 0; jt < 8; jt++) {
        const int j0 = jt * 64;
        // e tile: coalesced float4 loads, scalar row-major stores (stride 65)
        for (int idx = tid; idx < 32 * 16; idx += 256) {
            int i = idx >> 4, q = idx & 15;
            float4 ev = g_e4[(((size_t)b * LEN + i0 + i) * LEN + j0) / 4 + q];
            float* arow = As + i * ESTR + 4 * q;
            arow[0] = ev.x; arow[1] = ev.y; arow[2] = ev.z; arow[3] = ev.w;
        }
        // out tile
        for (int idx = tid; idx < 64 * 8; idx += 256) {
            int j = idx >> 3, q = idx & 7;
            *(float4*)(Bs + j * KSTR + 4 * q) =
                g_out4[((size_t)b * LEN + j0 + j) * 8 + q];
        }
        __syncthreads();

        // osum partials (each warp: its 4 h columns over all 64 rows)
#pragma unroll
        for (int c = 0; c < 4; c++)
            posum[c] += Bs[lane * KSTR + w4 + c] +
                        Bs[(lane + 32) * KSTR + w4 + c];

        // GEMM: ev scalar (bank i+jj: conflict-free), b4 broadcast
#pragma unroll 8
        for (int jj = 0; jj < 64; jj++) {
            const float ev = As[lane * ESTR + jj];
            const float4 b4 = *(const float4*)(Bs + jj * KSTR + w4);
            acc[0] = fmaf(ev, b4.x, acc[0]);
            acc[1] = fmaf(ev, b4.y, acc[1]);
            acc[2] = fmaf(ev, b4.z, acc[2]);
            acc[3] = fmaf(ev, b4.w, acc[3]);
        }
        __syncthreads();
    }

    // reduce osum partials across lanes
#pragma unroll
    for (int c = 0; c < 4; c++) {
        float t = posum[c];
#pragma unroll
        for (int s = 16; s > 0; s >>= 1)
            t += __shfl_xor_sync(0xffffffffu, t, s);
        if (lane == 0) osum_s[w4 + c] = t;
    }
    __syncthreads();

    // epilogue: lse per i (= lane), ctx = acc - lse*osum
    const float ps = g_ps[(b * 2 + 0) * LEN + i0 + lane] +
                     g_ps[(b * 2 + 1) * LEN + i0 + lane];
    const float lse = S + __logf(ps);
#pragma unroll
    for (int c = 0; c < 4; c++)
        cxs[lane][w4 + c] = fmaf(-lse, osum_s[w4 + c], acc[c]);
    __syncthreads();

    // fc head: 32 rows x 15 outputs
    for (int idx = tid; idx < 32 * ODIM; idx += 256) {
        const int i2 = idx / ODIM, o = idx % ODIM;
        float r = fcbs[o];
#pragma unroll
        for (int h = 0; h < HDIM; h++)
            r = fmaf(fcw[o][h], cxs[i2][h], r);
        y[((size_t)b * LEN + i0 + i2) * ODIM + o] = r;
    }
}

// ---------------------------------------------------------------------------
extern "C" void kernel_launch(void* const* d_in, const int* in_sizes, int n_in,
                              void* d_out, int out_size)
{
    const float* x      = (const float*)d_in[0];
    const int*   x_lens = (const int*)  d_in[1];
    const float* h0     = (const float*)d_in[2];
    const float* w_ih   = (const float*)d_in[3];
    const float* w_hh   = (const float*)d_in[4];
    const float* b_ih   = (const float*)d_in[5];
    const float* b_hh   = (const float*)d_in[6];
    const float* fc_w   = (const float*)d_in[7];
    const float* fc_b   = (const float*)d_in[8];
    const float* fch_w  = (const float*)d_in[9];
    const float* fco_w  = (const float*)d_in[10];
    const float* v      = (const float*)d_in[11];
    float* y = (float*)d_out;

    gx_kernel <<<(BATCH * LEN) / 64, 256>>>(x, w_ih, b_ih);
    gru_kernel<<<BATCH, 32>>>(w_hh, b_hh, h0, x_lens);
    qk_kernel <<<(BATCH * LEN) / 8, 256>>>(fch_w, fco_w);
    attn1_kernel<<<dim3(LEN / TI1, 2, BATCH), 256>>>(v, x_lens);
    attn2_kernel<<<dim3(LEN / 32, BATCH), 256>>>(v, fc_w, fc_b, y);
}

// round 11
// speedup vs baseline: 1.4413x; 1.2323x over previous
#include <cuda_runtime.h>

#define BATCH 16
#define LEN   512
#define IDIM  300
#define HDIM  32
#define ODIM  15
#define GDIM  96
#define JH    256         // keys per attn1 block (half)
#define TI1   16          // i-rows per attn1 block
#define KSTR  36          // smem row stride (floats), 16B-aligned
#define ESTR  65          // attn2 e-tile stride (odd -> conflict-free)
#define NKT   19          // gx k-steps (19*16 >= 300)

typedef unsigned long long ull;

// Scratch as float4 arrays (guarantees 16B alignment for vector access)
__device__ float4 g_gx4 [BATCH * LEN * GDIM / 4];
__device__ float4 g_out4[BATCH * LEN * HDIM / 4];
__device__ float4 g_qh4 [BATCH * LEN * HDIM / 4];
__device__ float4 g_kh4 [BATCH * LEN * HDIM / 4];
#define g_gx  ((float*)g_gx4)
#define g_out ((float*)g_out4)
#define g_qh  ((float*)g_qh4)
#define g_kh  ((float*)g_kh4)

__device__ float4 g_e4[BATCH * LEN * LEN / 4];       // raw e scores
#define g_e ((float*)g_e4)
__device__ float g_ps[BATCH * 2 * LEN];               // per-(row,half) sum exp(e-S)

__device__ __forceinline__ float tanh_fast(float x) {
    float y;
    asm("tanh.approx.f32 %0, %1;" : "=f"(y) : "f"(x));
    return y;
}
__device__ __forceinline__ ull ffma2u(ull a, ull b, ull c) {
    ull d;
    asm("fma.rn.f32x2 %0, %1, %2, %3;" : "=l"(d) : "l"(a), "l"(b), "l"(c));
    return d;
}
__device__ __forceinline__ ull add2u(ull a, ull b) {
    ull d;
    asm("add.rn.f32x2 %0, %1, %2;" : "=l"(d) : "l"(a), "l"(b));
    return d;
}
__device__ __forceinline__ ull pack2(float lo, float hi) {
    ull d;
    asm("mov.b64 %0, {%1, %2};" : "=l"(d) : "f"(lo), "f"(hi));
    return d;
}
__device__ __forceinline__ float hsum2(ull a) {
    float lo, hi;
    asm("mov.b64 {%0, %1}, %2;" : "=f"(lo), "=f"(hi) : "l"(a));
    return lo + hi;
}

// ---------------------------------------------------------------------------
// K1: gx = x @ w_ih^T + b_ih  (M=8192, N=96, K=300), double-buffered pipeline
// ---------------------------------------------------------------------------
__global__ __launch_bounds__(256) void gx_kernel(
    const float* __restrict__ x,
    const float* __restrict__ w_ih,
    const float* __restrict__ b_ih)
{
    __shared__ float xs[2][16][65];
    __shared__ float ws[2][16][97];

    const int tid = threadIdx.x;
    const int m0 = blockIdx.x * 64;
    const int tx = tid & 15;
    const int ty = tid >> 4;

    const int lr  = tid >> 2;       // load row (x) / col (w rows 0..63)
    const int lc4 = tid & 3;        // float4 slot within 16-k step

    float acc[4][6];
#pragma unroll
    for (int i = 0; i < 4; i++)
#pragma unroll
        for (int j = 0; j < 6; j++) acc[i][j] = 0.f;

    float4 xv, wv0, wv1;
    const float4 z4 = make_float4(0.f, 0.f, 0.f, 0.f);

#define GX_LOAD(IT) do {                                                     \
        const int kt = (IT) * 16;                                            \
        const bool ok = (kt + lc4 * 4 + 3) < IDIM;                           \
        xv  = ok ? *(const float4*)(x + (m0 + lr) * IDIM + kt + lc4 * 4)     \
                 : z4;                                                       \
        wv0 = ok ? *(const float4*)(w_ih + lr * IDIM + kt + lc4 * 4) : z4;   \
        if (tid < 128)                                                       \
            wv1 = ok ? *(const float4*)(w_ih + (64 + lr) * IDIM + kt +       \
                                        lc4 * 4) : z4;                       \
    } while (0)

#define GX_STORE(BUF) do {                                                   \
        xs[BUF][lc4 * 4 + 0][lr] = xv.x;                                     \
        xs[BUF][lc4 * 4 + 1][lr] = xv.y;                                     \
        xs[BUF][lc4 * 4 + 2][lr] = xv.z;                                     \
        xs[BUF][lc4 * 4 + 3][lr] = xv.w;                                     \
        ws[BUF][lc4 * 4 + 0][lr] = wv0.x;                                    \
        ws[BUF][lc4 * 4 + 1][lr] = wv0.y;                                    \
        ws[BUF][lc4 * 4 + 2][lr] = wv0.z;                                    \
        ws[BUF][lc4 * 4 + 3][lr] = wv0.w;                                    \
        if (tid < 128) {                                                     \
            ws[BUF][lc4 * 4 + 0][64 + lr] = wv1.x;                           \
            ws[BUF][lc4 * 4 + 1][64 + lr] = wv1.y;                           \
            ws[BUF][lc4 * 4 + 2][64 + lr] = wv1.z;                           \
            ws[BUF][lc4 * 4 + 3][64 + lr] = wv1.w;                           \
        }                                                                    \
    } while (0)

    GX_LOAD(0);
    GX_STORE(0);
    __syncthreads();

    for (int it = 0; it < NKT; it++) {
        const int cur = it & 1;
        if (it + 1 < NKT) GX_LOAD(it + 1);

#pragma unroll
        for (int kk = 0; kk < 16; kk++) {
            float xvv[4], wvv[6];
#pragma unroll
            for (int i = 0; i < 4; i++) xvv[i] = xs[cur][kk][ty * 4 + i];
#pragma unroll
            for (int j = 0; j < 6; j++) wvv[j] = ws[cur][kk][tx * 6 + j];
#pragma unroll
            for (int i = 0; i < 4; i++)
#pragma unroll
                for (int j = 0; j < 6; j++)
                    acc[i][j] = fmaf(xvv[i], wvv[j], acc[i][j]);
        }
        if (it + 1 < NKT) GX_STORE((it + 1) & 1);
        __syncthreads();
    }

#pragma unroll
    for (int i = 0; i < 4; i++) {
        int m = m0 + ty * 4 + i;
#pragma unroll
        for (int j = 0; j < 6; j++) {
            int c = tx * 6 + j;
            g_gx[m * GDIM + c] = acc[i][j] + b_ih[c];
        }
    }
}

// ---------------------------------------------------------------------------
// K2: GRU recurrence (proven R7/R10 version)
// ---------------------------------------------------------------------------
__global__ __launch_bounds__(32) void gru_kernel(
    const float* __restrict__ w_hh,
    const float* __restrict__ b_hh,
    const float* __restrict__ h0,
    const int*   __restrict__ x_lens)
{
    const int b = blockIdx.x;
    const int h = threadIdx.x;

    const ull* w8 = (const ull*)w_hh;   // [96][16] packed pairs
    ull wr2[16], wz2[16], wn2[16];
#pragma unroll
    for (int k = 0; k < 16; k++) {
        wr2[k] = w8[(0 * HDIM + h) * 16 + k];
        wz2[k] = w8[(1 * HDIM + h) * 16 + k];
        wn2[k] = w8[(2 * HDIM + h) * 16 + k];
    }
    const ull brp = pack2(b_hh[h], 0.f);
    const ull bzp = pack2(b_hh[HDIM + h], 0.f);
    const ull bnp = pack2(b_hh[2 * HDIM + h], 0.f);

    float hcur = h0[b * HDIM + h];
    float nb0 = __shfl_xor_sync(0xffffffffu, hcur, 1);
    ull hpair = (h & 1) ? pack2(nb0, hcur) : pack2(hcur, nb0);

    const int len = x_lens[b];
    const float* gxb = g_gx + (size_t)b * LEN * GDIM;
    float* outb = g_out + (size_t)b * LEN * HDIM;

    float rxb[4], zxb[4], nxb[4];
#pragma unroll
    for (int t = 0; t < 4; t++) {
        const float* p = gxb + t * GDIM;
        rxb[t] = p[h]; zxb[t] = p[HDIM + h]; nxb[t] = p[2 * HDIM + h];
    }

#pragma unroll 4
    for (int t = 0; t < LEN; t++) {
        const int s = t & 3;
        const float rx = rxb[s], zx = zxb[s], nx = nxb[s];
        if (t + 4 < LEN) {
            const float* p = gxb + (t + 4) * GDIM;
            rxb[s] = p[h]; zxb[s] = p[HDIM + h]; nxb[s] = p[2 * HDIM + h];
        }

        ull ra[4] = {brp, 0ull, 0ull, 0ull};
        ull za[4] = {bzp, 0ull, 0ull, 0ull};
        ull na[4] = {bnp, 0ull, 0ull, 0ull};
#pragma unroll
        for (int k = 0; k < 16; k++) {
            const ull h2 = __shfl_sync(0xffffffffu, hpair, 2 * k);
            const int p = k & 3;
            ra[p] = ffma2u(wr2[k], h2, ra[p]);
            za[p] = ffma2u(wz2[k], h2, za[p]);
            na[p] = ffma2u(wn2[k], h2, na[p]);
        }
        const float rh = hsum2(add2u(add2u(ra[0], ra[1]), add2u(ra[2], ra[3])));
        const float zh = hsum2(add2u(add2u(za[0], za[1]), add2u(za[2], za[3])));
        const float nh = hsum2(add2u(add2u(na[0], na[1]), add2u(na[2], na[3])));

        const float r = fmaf(tanh_fast((rx + rh) * 0.5f), 0.5f, 0.5f);
        const float z = fmaf(tanh_fast((zx + zh) * 0.5f), 0.5f, 0.5f);
        const float n = tanh_fast(fmaf(r, nh, nx));
        hcur = fmaf(z, hcur - n, n);

        const float nb = __shfl_xor_sync(0xffffffffu, hcur, 1);
        hpair = (h & 1) ? pack2(nb, hcur) : pack2(hcur, nb);

        outb[t * HDIM + h] = (t < len) ? hcur : 0.f;
    }
}

// ---------------------------------------------------------------------------
// K3: qh = out@fch_w^T, kh = out@fco_w^T
// ---------------------------------------------------------------------------
__global__ __launch_bounds__(256) void qk_kernel(
    const float* __restrict__ fch_w,
    const float* __restrict__ fco_w)
{
    __shared__ float wq[HDIM][HDIM + 1];
    __shared__ float wk[HDIM][HDIM + 1];
    __shared__ float os[8][HDIM];

    const int tid = threadIdx.x;
    for (int idx = tid; idx < HDIM * HDIM; idx += 256) {
        int c = idx >> 5, k = idx & 31;
        wq[k][c] = fch_w[c * HDIM + k];
        wk[k][c] = fco_w[c * HDIM + k];
    }
    const int m0 = blockIdx.x * 8;
    const int r = tid >> 5, c = tid & 31;
    os[r][c] = g_out[(m0 + r) * HDIM + c];
    __syncthreads();

    float aq = 0.f, ak = 0.f;
#pragma unroll
    for (int k = 0; k < HDIM; k++) {
        float o = os[r][k];
        aq = fmaf(o, wq[k][c], aq);
        ak = fmaf(o, wk[k][c], ak);
    }
    g_qh[(m0 + r) * HDIM + c] = aq;
    g_kh[(m0 + r) * HDIM + c] = ak;
}

// ---------------------------------------------------------------------------
// K4a: e scores + per-half exp-sums (unchanged from R10: 38us, occ 41%)
// ---------------------------------------------------------------------------
__global__ __launch_bounds__(256, 4) void attn1_kernel(
    const float* __restrict__ v,
    const int*   __restrict__ x_lens)
{
    __shared__ float ks[JH * KSTR];
    __shared__ float vsh[HDIM];

    const int b    = blockIdx.z;
    const int half = blockIdx.y;
    const int i0   = blockIdx.x * TI1;
    const int tid  = threadIdx.x;
    const int wid  = tid >> 5, lane = tid & 31;
    const int jbase = b * LEN + half * JH;

    for (int idx = tid; idx < JH * 8; idx += 256) {
        int j = idx >> 3, q = idx & 7;
        *(float4*)(ks + j * KSTR + q * 4) = g_kh4[(jbase + j) * 8 + q];
    }
    if (tid < HDIM) vsh[tid] = v[tid];
    __syncthreads();

    const int len    = x_lens[b];                     // 256..512
    const int kcount = half ? (len - JH) : JH;        // valid keys this half
    const int chunks = (kcount + 31) >> 5;            // 0..8
    const int tail   = JH - chunks * 32;

    const float vl = vsh[lane];
    float S = fabsf(vl);
#pragma unroll
    for (int s = 16; s > 0; s >>= 1)
        S += __shfl_xor_sync(0xffffffffu, S, s);

    for (int ii = wid; ii < TI1; ii += 8) {
        const int i = i0 + ii;
        const size_t row = (size_t)b * LEN + i;

        union { float4 v4[8]; float f[HDIM]; } qu;
#pragma unroll
        for (int q = 0; q < 8; q++)
            qu.v4[q] = g_qh4[row * 8 + q];

        float ep = 0.f;
        if (tail > 0) {
            ep = vl * tanh_fast(g_qh[row * HDIM + lane]);
#pragma unroll
            for (int s = 16; s > 0; s >>= 1)
                ep += __shfl_xor_sync(0xffffffffu, ep, s);
        }

        float* erow = g_e + row * LEN + half * JH;
        float ssum = 0.f;
        for (int c = 0; c < chunks; c++) {
            const float4* krow4 = (const float4*)(ks + (c * 32 + lane) * KSTR);
            float e = 0.f;
#pragma unroll
            for (int q = 0; q < 8; q++) {
                const float4 k4 = krow4[q];
                e = fmaf(vsh[4 * q + 0], tanh_fast(qu.f[4 * q + 0] + k4.x), e);
                e = fmaf(vsh[4 * q + 1], tanh_fast(qu.f[4 * q + 1] + k4.y), e);
                e = fmaf(vsh[4 * q + 2], tanh_fast(qu.f[4 * q + 2] + k4.z), e);
                e = fmaf(vsh[4 * q + 3], tanh_fast(qu.f[4 * q + 3] + k4.w), e);
            }
            ssum += __expf(e - S);
            erow[c * 32 + lane] = e;
        }
        for (int c = chunks; c < JH / 32; c++)
            erow[c * 32 + lane] = ep;

#pragma unroll
        for (int s = 16; s > 0; s >>= 1)
            ssum += __shfl_xor_sync(0xffffffffu, ssum, s);
        if (tail > 0) ssum += (float)tail * __expf(ep - S);
        if (lane == 0) g_ps[(b * 2 + half) * LEN + i] = ssum;
    }
}

// ---------------------------------------------------------------------------
// K4b: ctx GEMM, double-buffered tiles (one sync per j-tile), conflict-free
// smem, epilogue ctx = e@out - lse*osum, then fc head.
// ---------------------------------------------------------------------------
__global__ __launch_bounds__(256) void attn2_kernel(
    const float* __restrict__ v,
    const float* __restrict__ fc_w,
    const float* __restrict__ fc_b,
    float* __restrict__ y)
{
    __shared__ float As[2][32 * ESTR];    // e tile, row-major [i][j], stride 65
    __shared__ float Bs[2][64 * KSTR];    // out tile [j][h]
    __shared__ float osum_s[32];
    __shared__ float cxs[32][33];
    __shared__ float fcw[ODIM][33];
    __shared__ float fcbs[16];

    const int b    = blockIdx.y;
    const int i0   = blockIdx.x * 32;
    const int tid  = threadIdx.x;
    const int w    = tid >> 5;            // warp: h-group
    const int lane = tid & 31;            // local i
    const int w4   = w * 4;

    // load-slot indices (fixed per thread)
    const int eli = tid >> 4, elq = tid & 15;   // e: rows eli, eli+16
    const int olj = tid >> 3, olq = tid & 7;    // out: rows olj, olj+32

    for (int idx = tid; idx < ODIM * HDIM; idx += 256) {
        int o = idx / HDIM, h = idx % HDIM;
        fcw[o][h] = fc_w[idx];
    }
    if (tid < ODIM) fcbs[tid] = fc_b[tid];

    float S = fabsf(v[lane]);
#pragma unroll
    for (int s = 16; s > 0; s >>= 1)
        S += __shfl_xor_sync(0xffffffffu, S, s);

    float acc[4] = {0.f, 0.f, 0.f, 0.f};
    float posum[4] = {0.f, 0.f, 0.f, 0.f};

    float4 ev0, ev1, ov0, ov1;

#define A2_LOAD(JT) do {                                                     \
        const int j0n = (JT) * 64;                                           \
        ev0 = g_e4[(((size_t)b * LEN + i0 + eli) * LEN + j0n) / 4 + elq];    \
        ev1 = g_e4[(((size_t)b * LEN + i0 + 16 + eli) * LEN + j0n) / 4 + elq];\
        ov0 = g_out4[((size_t)b * LEN + j0n + olj) * 8 + olq];               \
        ov1 = g_out4[((size_t)b * LEN + j0n + 32 + olj) * 8 + olq];          \
    } while (0)

#define A2_STORE(BUF) do {                                                   \
        float* a0 = &As[BUF][eli * ESTR + 4 * elq];                          \
        a0[0] = ev0.x; a0[1] = ev0.y; a0[2] = ev0.z; a0[3] = ev0.w;          \
        float* a1 = &As[BUF][(eli + 16) * ESTR + 4 * elq];                   \
        a1[0] = ev1.x; a1[1] = ev1.y; a1[2] = ev1.z; a1[3] = ev1.w;          \
        *(float4*)&Bs[BUF][olj * KSTR + 4 * olq] = ov0;                      \
        *(float4*)&Bs[BUF][(olj + 32) * KSTR + 4 * olq] = ov1;               \
    } while (0)

    A2_LOAD(0);
    A2_STORE(0);
    __syncthreads();

    for (int jt = 0; jt < 8; jt++) {
        const int cur = jt & 1;
        if (jt < 7) A2_LOAD(jt + 1);

        // osum partials (each warp: its 4 h columns over all 64 rows)
#pragma unroll
        for (int c = 0; c < 4; c++)
            posum[c] += Bs[cur][lane * KSTR + w4 + c] +
                        Bs[cur][(lane + 32) * KSTR + w4 + c];

        // GEMM: ev scalar (conflict-free), b4 broadcast
#pragma unroll 8
        for (int jj = 0; jj < 64; jj++) {
            const float ev = As[cur][lane * ESTR + jj];
            const float4 b4 = *(const float4*)&Bs[cur][jj * KSTR + w4];
            acc[0] = fmaf(ev, b4.x, acc[0]);
            acc[1] = fmaf(ev, b4.y, acc[1]);
            acc[2] = fmaf(ev, b4.z, acc[2]);
            acc[3] = fmaf(ev, b4.w, acc[3]);
        }
        if (jt < 7) A2_STORE((jt + 1) & 1);
        __syncthreads();
    }

    // reduce osum partials across lanes
#pragma unroll
    for (int c = 0; c < 4; c++) {
        float t = posum[c];
#pragma unroll
        for (int s = 16; s > 0; s >>= 1)
            t += __shfl_xor_sync(0xffffffffu, t, s);
        if (lane == 0) osum_s[w4 + c] = t;
    }
    __syncthreads();

    // epilogue: lse per i (= lane), ctx = acc - lse*osum
    const float ps = g_ps[(b * 2 + 0) * LEN + i0 + lane] +
                     g_ps[(b * 2 + 1) * LEN + i0 + lane];
    const float lse = S + __logf(ps);
#pragma unroll
    for (int c = 0; c < 4; c++)
        cxs[lane][w4 + c] = fmaf(-lse, osum_s[w4 + c], acc[c]);
    __syncthreads();

    // fc head: 32 rows x 15 outputs
    for (int idx = tid; idx < 32 * ODIM; idx += 256) {
        const int i2 = idx / ODIM, o = idx % ODIM;
        float r = fcbs[o];
#pragma unroll
        for (int h = 0; h < HDIM; h++)
            r = fmaf(fcw[o][h], cxs[i2][h], r);
        y[((size_t)b * LEN + i0 + i2) * ODIM + o] = r;
    }
}

// ---------------------------------------------------------------------------
extern "C" void kernel_launch(void* const* d_in, const int* in_sizes, int n_in,
                              void* d_out, int out_size)
{
    const float* x      = (const float*)d_in[0];
    const int*   x_lens = (const int*)  d_in[1];
    const float* h0     = (const float*)d_in[2];
    const float* w_ih   = (const float*)d_in[3];
    const float* w_hh   = (const float*)d_in[4];
    const float* b_ih   = (const float*)d_in[5];
    const float* b_hh   = (const float*)d_in[6];
    const float* fc_w   = (const float*)d_in[7];
    const float* fc_b   = (const float*)d_in[8];
    const float* fch_w  = (const float*)d_in[9];
    const float* fco_w  = (const float*)d_in[10];
    const float* v      = (const float*)d_in[11];
    float* y = (float*)d_out;

    gx_kernel <<<(BATCH * LEN) / 64, 256>>>(x, w_ih, b_ih);
    gru_kernel<<<BATCH, 32>>>(w_hh, b_hh, h0, x_lens);
    qk_kernel <<<(BATCH * LEN) / 8, 256>>>(fch_w, fco_w);
    attn1_kernel<<<dim3(LEN / TI1, 2, BATCH), 256>>>(v, x_lens);
    attn2_kernel<<<dim3(LEN / 32, BATCH), 256>>>(v, fc_w, fc_b, y);
}